// round 5
// baseline (speedup 1.0000x reference)
#include <cuda_runtime.h>
#include <math.h>

// Problem constants
#define NN   16384
#define HID  128
#define PROP 64
#define SPACE 4
#define KNB  40
#define NLAYERS 4

// Scratch (static device allocations; no cudaMalloc allowed)
__device__ float g_x[NN * HID];
__device__ float g_y[NN * HID];
__device__ float g_s[NN * SPACE];
__device__ float g_h[NN * PROP];
__device__ float g_agg[NN * HID];
__device__ float g_w[NN * KNB];
__device__ int   g_idx[NN * KNB];

// Device-side buffer resolution: keeps kernel_launch free of any host API
// besides kernel launches (no cudaGetSymbolAddress during graph capture).
// ids: 0=g_x, 1=g_y, 2=g_agg, 3=g_h, 4=g_s, -1=use provided pointer.
__device__ __forceinline__ const float* resolve_c(const float* p, int id) {
    switch (id) {
        case 0: return g_x;
        case 1: return g_y;
        case 2: return g_agg;
        case 3: return g_h;
        case 4: return g_s;
        default: return p;
    }
}
__device__ __forceinline__ float* resolve_w(float* p, int id) {
    switch (id) {
        case 0: return g_x;
        case 1: return g_y;
        case 2: return g_agg;
        case 3: return g_h;
        case 4: return g_s;
        default: return p;
    }
}

// ---------------------------------------------------------------------------
// Tiled SGEMM: C[N x MD] = act(A[N x KD] @ W[KD x MD] + b)
// Block = MD threads, each thread owns one output column for 32 rows.
// A tile staged in shared; A reads are warp-broadcast LDS.128; W reads coalesced.
// ---------------------------------------------------------------------------
template <int KD, int MD, bool RELU>
__global__ void __launch_bounds__(MD) gemm_k(const float* __restrict__ Ap, int aid,
                                             const float* __restrict__ W,
                                             const float* __restrict__ B,
                                             float* __restrict__ Cp, int cid) {
    const float* __restrict__ A = resolve_c(Ap, aid);
    float* __restrict__ C = resolve_w(Cp, cid);

    __shared__ float As[32 * KD];
    const int c = threadIdx.x;
    const int row0 = blockIdx.x * 32;

    for (int i = c; i < 32 * KD; i += MD) As[i] = A[row0 * KD + i];
    __syncthreads();

    float acc[32];
#pragma unroll
    for (int r = 0; r < 32; ++r) acc[r] = 0.f;

    if constexpr (KD % 4 == 0) {
        for (int k = 0; k < KD; k += 4) {
            float w0 = W[(k + 0) * MD + c];
            float w1 = W[(k + 1) * MD + c];
            float w2 = W[(k + 2) * MD + c];
            float w3 = W[(k + 3) * MD + c];
#pragma unroll
            for (int r = 0; r < 32; ++r) {
                float4 a = *reinterpret_cast<const float4*>(&As[r * KD + k]);
                float v = acc[r];
                v = fmaf(a.x, w0, v);
                v = fmaf(a.y, w1, v);
                v = fmaf(a.z, w2, v);
                v = fmaf(a.w, w3, v);
                acc[r] = v;
            }
        }
    } else {
        for (int k = 0; k < KD; ++k) {
            float wv = W[k * MD + c];
#pragma unroll
            for (int r = 0; r < 32; ++r) acc[r] = fmaf(As[r * KD + k], wv, acc[r]);
        }
    }

    float bb = B[c];
#pragma unroll
    for (int r = 0; r < 32; ++r) {
        float v = acc[r] + bb;
        if (RELU) v = fmaxf(v, 0.f);
        C[(row0 + r) * MD + c] = v;
    }
}

// ---------------------------------------------------------------------------
// Two-source SGEMM for lin_out: g_x = [g_y | g_agg] @ W + b, KD = 256, MD = 128.
// Avoids materializing the concat. Sources/dest hardcoded to globals.
// ---------------------------------------------------------------------------
__global__ void __launch_bounds__(128) gemm2_k(const float* __restrict__ W,
                                               const float* __restrict__ B) {
    const float* __restrict__ A1 = g_y;
    const float* __restrict__ A2 = g_agg;
    float* __restrict__ C = g_x;

    __shared__ float As[32 * 256];
    const int c = threadIdx.x;
    const int row0 = blockIdx.x * 32;

    for (int i = c; i < 32 * 128; i += 128) {
        int r = i >> 7, k = i & 127;
        As[r * 256 + k]       = A1[(row0 + r) * 128 + k];
        As[r * 256 + 128 + k] = A2[(row0 + r) * 128 + k];
    }
    __syncthreads();

    float acc[32];
#pragma unroll
    for (int r = 0; r < 32; ++r) acc[r] = 0.f;

    for (int k = 0; k < 256; k += 4) {
        float w0 = W[(k + 0) * 128 + c];
        float w1 = W[(k + 1) * 128 + c];
        float w2 = W[(k + 2) * 128 + c];
        float w3 = W[(k + 3) * 128 + c];
#pragma unroll
        for (int r = 0; r < 32; ++r) {
            float4 a = *reinterpret_cast<const float4*>(&As[r * 256 + k]);
            float v = acc[r];
            v = fmaf(a.x, w0, v);
            v = fmaf(a.y, w1, v);
            v = fmaf(a.z, w2, v);
            v = fmaf(a.w, w3, v);
            acc[r] = v;
        }
    }

    float bb = B[c];
#pragma unroll
    for (int r = 0; r < 32; ++r) {
        C[(row0 + r) * 128 + c] = acc[r] + bb;
    }
}

// ---------------------------------------------------------------------------
// Small GEMM: C[N x 4] = act(A[N x 128] @ W[128 x 4] + b). Thread = (row, col).
// Padded shared tile to avoid bank conflicts.
// ---------------------------------------------------------------------------
template <bool RELU>
__global__ void __launch_bounds__(128) gemm4_k(const float* __restrict__ Ap, int aid,
                                               const float* __restrict__ W,
                                               const float* __restrict__ B,
                                               float* __restrict__ Cp, int cid) {
    const float* __restrict__ A = resolve_c(Ap, aid);
    float* __restrict__ C = resolve_w(Cp, cid);

    __shared__ float As[32][132];
    const int t = threadIdx.x;
    const int row0 = blockIdx.x * 32;

    for (int i = t; i < 32 * 128; i += 128) As[i >> 7][i & 127] = A[row0 * 128 + i];
    __syncthreads();

    const int r = t >> 2, c = t & 3;
    float acc = 0.f;
#pragma unroll 8
    for (int k = 0; k < 128; ++k) acc = fmaf(As[r][k], W[k * 4 + c], acc);

    float v = acc + B[c];
    if (RELU) v = fmaxf(v, 0.f);
    C[(row0 + r) * 4 + c] = v;
}

// ---------------------------------------------------------------------------
// kNN: for each row, 40 nearest neighbors in 4-D s-space (self included).
// 4 threads per row, each scanning a j-residue class (j % 4 == sub) over shared
// tiles; per-thread sorted top-40 in local memory; 4-way merge in shared
// (stride 161 padding -> conflict-free across lanes).
// Reads g_s; writes g_idx and g_w = exp(-10 * max(d2, 0)).
// ---------------------------------------------------------------------------
__global__ void __launch_bounds__(128) knn_k() {
    const float* __restrict__ S = g_s;
    int* __restrict__ IDX = g_idx;
    float* __restrict__ WW = g_w;

    constexpr int TJ = 256;
    __shared__ float4 sj[TJ];
    __shared__ float  s2j[TJ];
    __shared__ float  md[32][161];
    __shared__ int    mi[32][161];

    const int t   = threadIdx.x;
    const int rl  = t & 31;   // local row (warp lane)
    const int sub = t >> 5;   // residue class (one per warp)
    const int row = blockIdx.x * 32 + rl;

    const float4 si = reinterpret_cast<const float4*>(S)[row];
    const float s2i = si.x * si.x + si.y * si.y + si.z * si.z + si.w * si.w;

    float bd[KNB];
    int   bi[KNB];
#pragma unroll
    for (int k = 0; k < KNB; ++k) { bd[k] = 3.4e38f; bi[k] = 0; }
    float worst = 3.4e38f;

    for (int base = 0; base < NN; base += TJ) {
        __syncthreads();
        for (int i = t; i < TJ; i += 128) {
            float4 v = reinterpret_cast<const float4*>(S)[base + i];
            sj[i] = v;
            s2j[i] = v.x * v.x + v.y * v.y + v.z * v.z + v.w * v.w;
        }
        __syncthreads();

#pragma unroll 4
        for (int jj = sub; jj < TJ; jj += 4) {
            float4 vj = sj[jj];
            float dot = si.x * vj.x;
            dot = fmaf(si.y, vj.y, dot);
            dot = fmaf(si.z, vj.z, dot);
            dot = fmaf(si.w, vj.w, dot);
            float d = s2i + s2j[jj] - 2.f * dot;
            if (d < worst) {
                int p = KNB - 1;
                while (p > 0 && bd[p - 1] > d) {
                    bd[p] = bd[p - 1];
                    bi[p] = bi[p - 1];
                    --p;
                }
                bd[p] = d;
                bi[p] = base + jj;
                worst = bd[KNB - 1];
            }
        }
    }

    // dump per-thread sorted lists to shared (conflict-free: bank index == rl)
#pragma unroll
    for (int k = 0; k < KNB; ++k) {
        md[rl][sub * KNB + k] = bd[k];
        mi[rl][sub * KNB + k] = bi[k];
    }
    __syncthreads();

    // warp 0 (sub == 0) merges the 4 sorted lists per row
    if (sub == 0) {
        int p0 = 0, p1 = 0, p2 = 0, p3 = 0;
        for (int k = 0; k < KNB; ++k) {
            float d0 = md[rl][0 * KNB + p0];
            float d1 = md[rl][1 * KNB + p1];
            float d2v = md[rl][2 * KNB + p2];
            float d3 = md[rl][3 * KNB + p3];
            float dm = d0;
            int sm = 0;
            if (d1 < dm) { dm = d1; sm = 1; }
            if (d2v < dm) { dm = d2v; sm = 2; }
            if (d3 < dm) { dm = d3; sm = 3; }
            int ji;
            if (sm == 0)      ji = mi[rl][0 * KNB + p0++];
            else if (sm == 1) ji = mi[rl][1 * KNB + p1++];
            else if (sm == 2) ji = mi[rl][2 * KNB + p2++];
            else              ji = mi[rl][3 * KNB + p3++];
            IDX[row * KNB + k] = ji;
            WW[row * KNB + k] = expf(-10.f * fmaxf(dm, 0.f));
        }
    }
}

// ---------------------------------------------------------------------------
// Aggregation: g_agg[i] = [mean_k(g_h[idx_k] * w_k), max_k(g_h[idx_k] * w_k)]
// 4 rows per block, 64 threads (one per PROP dim) per row. h-gathers are
// coalesced 256B per neighbor and L2-resident (h = 4 MB).
// ---------------------------------------------------------------------------
__global__ void __launch_bounds__(256) agg_k() {
    const float* __restrict__ H = g_h;
    const int* __restrict__ IDX = g_idx;
    const float* __restrict__ WW = g_w;
    float* __restrict__ AGG = g_agg;

    __shared__ int   sidx[4][KNB];
    __shared__ float sw[4][KNB];
    const int t = threadIdx.x;
    const int r = t >> 6;
    const int d = t & 63;
    const int row = blockIdx.x * 4 + r;

    if (d < KNB) {
        sidx[r][d] = IDX[row * KNB + d];
        sw[r][d] = WW[row * KNB + d];
    }
    __syncthreads();

    float sum = 0.f, mx = -3.4e38f;
#pragma unroll 4
    for (int k = 0; k < KNB; ++k) {
        int j = sidx[r][k];
        float v = H[j * PROP + d] * sw[r][k];
        sum += v;
        mx = fmaxf(mx, v);
    }
    AGG[row * HID + d]      = sum * (1.f / 40.f);
    AGG[row * HID + 64 + d] = mx;
}

// ---------------------------------------------------------------------------
// Host: full pipeline as a chain of kernel launches (graph-capturable).
// NOTHING but kernel launches here — scratch buffers resolved device-side.
// ---------------------------------------------------------------------------
extern "C" void kernel_launch(void* const* d_in, const int* in_sizes, int n_in,
                              void* d_out, int out_size) {
    const float* x_in  = (const float*)d_in[0];
    const float* fc1_W = (const float*)d_in[1];
    const float* fc1_b = (const float*)d_in[2];
    const float* fc2_W = (const float*)d_in[3];
    const float* fc2_b = (const float*)d_in[4];
    const float* gs_W  = (const float*)d_in[5];
    const float* gs_b  = (const float*)d_in[6];
    const float* gh_W  = (const float*)d_in[7];
    const float* gh_b  = (const float*)d_in[8];
    const float* go_W  = (const float*)d_in[9];
    const float* go_b  = (const float*)d_in[10];
    const float* d1_W  = (const float*)d_in[11];
    const float* d1_b  = (const float*)d_in[12];
    const float* d2_W  = (const float*)d_in[13];
    const float* d2_b  = (const float*)d_in[14];
    const float* d3_W  = (const float*)d_in[15];
    const float* d3_b  = (const float*)d_in[16];
    const float* fc3_W = (const float*)d_in[17];
    const float* fc3_b = (const float*)d_in[18];
    const float* fc4_W = (const float*)d_in[19];
    const float* fc4_b = (const float*)d_in[20];
    float* out = (float*)d_out;

    const int GB = NN / 32;  // 512 blocks

    // fc1: x_in -> g_x(relu), fc2: g_x -> g_y(relu)
    gemm_k<9, 128, true><<<GB, 128>>>(x_in, -1, fc1_W, fc1_b, nullptr, 0);
    gemm_k<128, 128, true><<<GB, 128>>>(nullptr, 0, fc2_W, fc2_b, nullptr, 1);

    // x lives in g_y across layers; g_x is the ping-pong scratch.
    for (int i = 0; i < NLAYERS; ++i) {
        gemm4_k<false><<<GB, 128>>>(nullptr, 1, gs_W + i * HID * SPACE, gs_b + i * SPACE, nullptr, 4);
        gemm_k<128, 64, false><<<GB, 64>>>(nullptr, 1, gh_W + i * HID * PROP, gh_b + i * PROP, nullptr, 3);
        knn_k<<<GB, 128>>>();
        agg_k<<<NN / 4, 256>>>();
        gemm2_k<<<GB, 128>>>(go_W + i * 2 * HID * HID, go_b + i * HID);               // [g_y|g_agg] -> g_x
        gemm_k<128, 128, true><<<GB, 128>>>(nullptr, 0, d1_W + i * HID * HID, d1_b + i * HID, nullptr, 1);
        gemm_k<128, 128, true><<<GB, 128>>>(nullptr, 1, d2_W + i * HID * HID, d2_b + i * HID, nullptr, 0);
        gemm_k<128, 128, true><<<GB, 128>>>(nullptr, 0, d3_W + i * HID * HID, d3_b + i * HID, nullptr, 1);
    }

    // fc3: g_y -> g_x(relu), fc4: g_x -> out
    gemm_k<128, 128, true><<<GB, 128>>>(nullptr, 1, fc3_W, fc3_b, nullptr, 0);
    gemm4_k<false><<<GB, 128>>>(nullptr, 0, fc4_W, fc4_b, out, -1);
}

// round 7
// speedup vs baseline: 13.5131x; 13.5131x over previous
#include <cuda_runtime.h>
#include <math.h>

// Problem constants
#define NN   16384
#define HID  128
#define PROP 64
#define SPACE 4
#define KNB  40
#define NLAYERS 4
#define FULLMASK 0xFFFFFFFFu

// Scratch (static device allocations; no cudaMalloc allowed)
__device__ float g_x[NN * HID];
__device__ float g_y[NN * HID];
__device__ float g_s[NN * SPACE];
__device__ float g_h[NN * PROP];
__device__ float g_agg[NN * HID];
__device__ float g_w[NN * KNB];
__device__ int   g_idx[NN * KNB];

// Device-side buffer resolution: keeps kernel_launch free of any host API
// besides kernel launches. ids: 0=g_x, 1=g_y, 2=g_agg, 3=g_h, 4=g_s, -1=arg.
__device__ __forceinline__ const float* resolve_c(const float* p, int id) {
    switch (id) {
        case 0: return g_x;
        case 1: return g_y;
        case 2: return g_agg;
        case 3: return g_h;
        case 4: return g_s;
        default: return p;
    }
}
__device__ __forceinline__ float* resolve_w(float* p, int id) {
    switch (id) {
        case 0: return g_x;
        case 1: return g_y;
        case 2: return g_agg;
        case 3: return g_h;
        case 4: return g_s;
        default: return p;
    }
}

// ---------------------------------------------------------------------------
// Tiled SGEMM: C[N x MD] = act(A[N x KD] @ W[KD x MD] + b)
// Block = 2*MD threads: thread (c, h) owns column c for rows h*16..h*16+15.
// A tile in shared (warp-broadcast LDS.128); W coalesced LDG with depth-1
// prefetch; 2x warps vs round-5 version for latency hiding.
// ---------------------------------------------------------------------------
template <int KD, int MD, bool RELU>
__global__ void __launch_bounds__(2 * MD) gemm_k(const float* __restrict__ Ap, int aid,
                                                 const float* __restrict__ W,
                                                 const float* __restrict__ B,
                                                 float* __restrict__ Cp, int cid) {
    const float* __restrict__ A = resolve_c(Ap, aid);
    float* __restrict__ C = resolve_w(Cp, cid);

    __shared__ float As[32 * KD];
    const int t = threadIdx.x;
    const int c = t % MD;
    const int h = t / MD;
    const int row0 = blockIdx.x * 32;

    {
        const float4* src = reinterpret_cast<const float4*>(A + row0 * KD);
        float4* dst = reinterpret_cast<float4*>(As);
        for (int i = t; i < 8 * KD; i += 2 * MD) dst[i] = src[i];
    }
    __syncthreads();

    float acc[16];
#pragma unroll
    for (int r = 0; r < 16; ++r) acc[r] = 0.f;

    const float* Asb = As + (h * 16) * KD;

    if constexpr (KD % 4 == 0) {
        float w0 = W[0 * MD + c], w1 = W[1 * MD + c];
        float w2 = W[2 * MD + c], w3 = W[3 * MD + c];
        for (int k = 0; k < KD; k += 4) {
            float n0 = 0.f, n1 = 0.f, n2 = 0.f, n3 = 0.f;
            if (k + 4 < KD) {
                n0 = W[(k + 4) * MD + c];
                n1 = W[(k + 5) * MD + c];
                n2 = W[(k + 6) * MD + c];
                n3 = W[(k + 7) * MD + c];
            }
#pragma unroll
            for (int r = 0; r < 16; ++r) {
                float4 a = *reinterpret_cast<const float4*>(&Asb[r * KD + k]);
                float v = acc[r];
                v = fmaf(a.x, w0, v);
                v = fmaf(a.y, w1, v);
                v = fmaf(a.z, w2, v);
                v = fmaf(a.w, w3, v);
                acc[r] = v;
            }
            w0 = n0; w1 = n1; w2 = n2; w3 = n3;
        }
    } else {
        for (int k = 0; k < KD; ++k) {
            float wv = W[k * MD + c];
#pragma unroll
            for (int r = 0; r < 16; ++r) acc[r] = fmaf(Asb[r * KD + k], wv, acc[r]);
        }
    }

    float bb = B[c];
#pragma unroll
    for (int r = 0; r < 16; ++r) {
        float v = acc[r] + bb;
        if (RELU) v = fmaxf(v, 0.f);
        C[(row0 + h * 16 + r) * MD + c] = v;
    }
}

// ---------------------------------------------------------------------------
// Two-source SGEMM for lin_out: g_x = [g_y | g_agg] @ W + b, KD=256, MD=128.
// ---------------------------------------------------------------------------
__global__ void __launch_bounds__(256) gemm2_k(const float* __restrict__ W,
                                               const float* __restrict__ B) {
    const float* __restrict__ A1 = g_y;
    const float* __restrict__ A2 = g_agg;
    float* __restrict__ C = g_x;

    __shared__ float As[32 * 256];
    const int t = threadIdx.x;
    const int c = t % 128;
    const int h = t / 128;
    const int row0 = blockIdx.x * 32;

    {
        const float4* s1 = reinterpret_cast<const float4*>(A1 + row0 * 128);
        const float4* s2 = reinterpret_cast<const float4*>(A2 + row0 * 128);
        float4* dst = reinterpret_cast<float4*>(As);
        for (int i = t; i < 32 * 32; i += 256) {
            int r = i >> 5, kq = i & 31;
            dst[r * 64 + kq]      = s1[r * 32 + kq];
            dst[r * 64 + 32 + kq] = s2[r * 32 + kq];
        }
    }
    __syncthreads();

    float acc[16];
#pragma unroll
    for (int r = 0; r < 16; ++r) acc[r] = 0.f;

    const float* Asb = As + (h * 16) * 256;

    float w0 = W[0 * 128 + c], w1 = W[1 * 128 + c];
    float w2 = W[2 * 128 + c], w3 = W[3 * 128 + c];
    for (int k = 0; k < 256; k += 4) {
        float n0 = 0.f, n1 = 0.f, n2 = 0.f, n3 = 0.f;
        if (k + 4 < 256) {
            n0 = W[(k + 4) * 128 + c];
            n1 = W[(k + 5) * 128 + c];
            n2 = W[(k + 6) * 128 + c];
            n3 = W[(k + 7) * 128 + c];
        }
#pragma unroll
        for (int r = 0; r < 16; ++r) {
            float4 a = *reinterpret_cast<const float4*>(&Asb[r * 256 + k]);
            float v = acc[r];
            v = fmaf(a.x, w0, v);
            v = fmaf(a.y, w1, v);
            v = fmaf(a.z, w2, v);
            v = fmaf(a.w, w3, v);
            acc[r] = v;
        }
        w0 = n0; w1 = n1; w2 = n2; w3 = n3;
    }

    float bb = B[c];
#pragma unroll
    for (int r = 0; r < 16; ++r) {
        C[(row0 + h * 16 + r) * 128 + c] = acc[r] + bb;
    }
}

// ---------------------------------------------------------------------------
// Small GEMM: C[N x 4] = act(A[N x 128] @ W[128 x 4] + b).
// ---------------------------------------------------------------------------
template <bool RELU>
__global__ void __launch_bounds__(128) gemm4_k(const float* __restrict__ Ap, int aid,
                                               const float* __restrict__ W,
                                               const float* __restrict__ B,
                                               float* __restrict__ Cp, int cid) {
    const float* __restrict__ A = resolve_c(Ap, aid);
    float* __restrict__ C = resolve_w(Cp, cid);

    __shared__ float As[32][132];
    const int t = threadIdx.x;
    const int row0 = blockIdx.x * 32;

    for (int i = t; i < 32 * 128; i += 128) As[i >> 7][i & 127] = A[row0 * 128 + i];
    __syncthreads();

    const int r = t >> 2, c = t & 3;
    float acc = 0.f;
#pragma unroll 8
    for (int k = 0; k < 128; ++k) acc = fmaf(As[r][k], W[k * 4 + c], acc);

    float v = acc + B[c];
    if (RELU) v = fmaxf(v, 0.f);
    C[(row0 + r) * 4 + c] = v;
}

// ---------------------------------------------------------------------------
// kNN v2: warp-per-row, register-distributed top-40, NO local-memory arrays.
// Lane l holds buffer slot0 (all 32 lanes) + slot1 (lanes 0..7) -> 40 slots.
// Per step: 32 distances vs shared tile; ballot selects d < worst (rare);
// each passing candidate replaces the warp-argmax slot via shfl reduction.
// ---------------------------------------------------------------------------
__global__ void __launch_bounds__(256) knn_k() {
    const float* __restrict__ S = g_s;
    int* __restrict__ IDX = g_idx;
    float* __restrict__ WW = g_w;

    constexpr int TJ = 512;
    __shared__ float4 sj[TJ];
    __shared__ float  s2j[TJ];

    const int t = threadIdx.x;
    const int lane = t & 31;
    const int wrp = t >> 5;                 // 8 warps = 8 rows per block
    const int row = blockIdx.x * 8 + wrp;

    const float4 si = reinterpret_cast<const float4*>(S)[row];
    float s2i = si.x * si.x;
    s2i = fmaf(si.y, si.y, s2i);
    s2i = fmaf(si.z, si.z, s2i);
    s2i = fmaf(si.w, si.w, s2i);

    const float INFP = __int_as_float(0x7f800000);
    const float INFN = __int_as_float(0xff800000);

    float bd0 = INFP;
    float bd1 = (lane < 8) ? INFP : INFN;   // -inf sentinel: never argmax
    int bi0 = 0, bi1 = 0;
    float worst = INFP;

    for (int base = 0; base < NN; base += TJ) {
        __syncthreads();
        for (int i = t; i < TJ; i += 256) {
            float4 v = reinterpret_cast<const float4*>(S)[base + i];
            float s2 = v.x * v.x;
            s2 = fmaf(v.y, v.y, s2);
            s2 = fmaf(v.z, v.z, s2);
            s2 = fmaf(v.w, v.w, s2);
            sj[i] = v;
            s2j[i] = s2;
        }
        __syncthreads();

        for (int stp = 0; stp < TJ; stp += 32) {
            const int jj = stp + lane;
            float4 vj = sj[jj];
            float dot = si.x * vj.x;
            dot = fmaf(si.y, vj.y, dot);
            dot = fmaf(si.z, vj.z, dot);
            dot = fmaf(si.w, vj.w, dot);
            float d = s2i + s2j[jj] - 2.f * dot;
            int j = base + jj;

            unsigned mask = __ballot_sync(FULLMASK, d < worst);
            while (mask) {
                int src = __ffs(mask) - 1;
                mask &= mask - 1;
                float dc = __shfl_sync(FULLMASK, d, src);
                int jc = __shfl_sync(FULLMASK, j, src);
                if (dc < worst) {
                    // warp argmax over 40 buffer slots
                    float bm = fmaxf(bd0, bd1);
                    int bl = lane;
#pragma unroll
                    for (int off = 16; off; off >>= 1) {
                        float om = __shfl_xor_sync(FULLMASK, bm, off);
                        int ol = __shfl_xor_sync(FULLMASK, bl, off);
                        if (om > bm || (om == bm && ol < bl)) { bm = om; bl = ol; }
                    }
                    if (lane == bl) {
                        if (bd0 >= bd1) { bd0 = dc; bi0 = jc; }
                        else            { bd1 = dc; bi1 = jc; }
                    }
                    // new worst
                    float m2 = fmaxf(bd0, bd1);
#pragma unroll
                    for (int off = 16; off; off >>= 1)
                        m2 = fmaxf(m2, __shfl_xor_sync(FULLMASK, m2, off));
                    worst = m2;
                }
            }
        }
    }

    // write out the 40 slots (aggregation is order-invariant)
    IDX[row * KNB + lane] = bi0;
    WW[row * KNB + lane] = expf(-10.f * fmaxf(bd0, 0.f));
    if (lane < 8) {
        IDX[row * KNB + 32 + lane] = bi1;
        WW[row * KNB + 32 + lane] = expf(-10.f * fmaxf(bd1, 0.f));
    }
}

// ---------------------------------------------------------------------------
// Aggregation: g_agg[i] = [mean_k(g_h[idx_k] * w_k), max_k(g_h[idx_k] * w_k)]
// ---------------------------------------------------------------------------
__global__ void __launch_bounds__(256) agg_k() {
    const float* __restrict__ H = g_h;
    const int* __restrict__ IDX = g_idx;
    const float* __restrict__ WW = g_w;
    float* __restrict__ AGG = g_agg;

    __shared__ int   sidx[4][KNB];
    __shared__ float sw[4][KNB];
    const int t = threadIdx.x;
    const int r = t >> 6;
    const int d = t & 63;
    const int row = blockIdx.x * 4 + r;

    if (d < KNB) {
        sidx[r][d] = IDX[row * KNB + d];
        sw[r][d] = WW[row * KNB + d];
    }
    __syncthreads();

    float sum = 0.f, mx = -3.4e38f;
#pragma unroll 4
    for (int k = 0; k < KNB; ++k) {
        int j = sidx[r][k];
        float v = H[j * PROP + d] * sw[r][k];
        sum += v;
        mx = fmaxf(mx, v);
    }
    AGG[row * HID + d]      = sum * (1.f / 40.f);
    AGG[row * HID + 64 + d] = mx;
}

// ---------------------------------------------------------------------------
// Host: full pipeline as a chain of kernel launches (graph-capturable).
// ---------------------------------------------------------------------------
extern "C" void kernel_launch(void* const* d_in, const int* in_sizes, int n_in,
                              void* d_out, int out_size) {
    const float* x_in  = (const float*)d_in[0];
    const float* fc1_W = (const float*)d_in[1];
    const float* fc1_b = (const float*)d_in[2];
    const float* fc2_W = (const float*)d_in[3];
    const float* fc2_b = (const float*)d_in[4];
    const float* gs_W  = (const float*)d_in[5];
    const float* gs_b  = (const float*)d_in[6];
    const float* gh_W  = (const float*)d_in[7];
    const float* gh_b  = (const float*)d_in[8];
    const float* go_W  = (const float*)d_in[9];
    const float* go_b  = (const float*)d_in[10];
    const float* d1_W  = (const float*)d_in[11];
    const float* d1_b  = (const float*)d_in[12];
    const float* d2_W  = (const float*)d_in[13];
    const float* d2_b  = (const float*)d_in[14];
    const float* d3_W  = (const float*)d_in[15];
    const float* d3_b  = (const float*)d_in[16];
    const float* fc3_W = (const float*)d_in[17];
    const float* fc3_b = (const float*)d_in[18];
    const float* fc4_W = (const float*)d_in[19];
    const float* fc4_b = (const float*)d_in[20];
    float* out = (float*)d_out;

    const int GB = NN / 32;  // 512 blocks

    // fc1: x_in -> g_x(relu), fc2: g_x -> g_y(relu)
    gemm_k<9, 128, true><<<GB, 256>>>(x_in, -1, fc1_W, fc1_b, nullptr, 0);
    gemm_k<128, 128, true><<<GB, 256>>>(nullptr, 0, fc2_W, fc2_b, nullptr, 1);

    // x lives in g_y across layers; g_x is the ping-pong scratch.
    for (int i = 0; i < NLAYERS; ++i) {
        gemm4_k<false><<<GB, 128>>>(nullptr, 1, gs_W + i * HID * SPACE, gs_b + i * SPACE, nullptr, 4);
        gemm_k<128, 64, false><<<GB, 128>>>(nullptr, 1, gh_W + i * HID * PROP, gh_b + i * PROP, nullptr, 3);
        knn_k<<<NN / 8, 256>>>();
        agg_k<<<NN / 4, 256>>>();
        gemm2_k<<<GB, 256>>>(go_W + i * 2 * HID * HID, go_b + i * HID);  // [g_y|g_agg] -> g_x
        gemm_k<128, 128, true><<<GB, 256>>>(nullptr, 0, d1_W + i * HID * HID, d1_b + i * HID, nullptr, 1);
        gemm_k<128, 128, true><<<GB, 256>>>(nullptr, 1, d2_W + i * HID * HID, d2_b + i * HID, nullptr, 0);
        gemm_k<128, 128, true><<<GB, 256>>>(nullptr, 0, d3_W + i * HID * HID, d3_b + i * HID, nullptr, 1);
    }

    // fc3: g_y -> g_x(relu), fc4: g_x -> out
    gemm_k<128, 128, true><<<GB, 256>>>(nullptr, 1, fc3_W, fc3_b, nullptr, 0);
    gemm4_k<false><<<GB, 128>>>(nullptr, 0, fc4_W, fc4_b, out, -1);
}

// round 8
// speedup vs baseline: 29.9648x; 2.2175x over previous
#include <cuda_runtime.h>
#include <math.h>

// Problem constants
#define NN   16384
#define HID  128
#define PROP 64
#define SPACE 4
#define KNB  40
#define NLAYERS 4
#define FULLMASK 0xFFFFFFFFu

// Scratch (static device allocations; no cudaMalloc allowed)
__device__ float g_x[NN * HID];
__device__ float g_y[NN * HID];
__device__ float g_s[NN * SPACE];
__device__ float g_h[NN * PROP];
__device__ float g_agg[NN * HID];
__device__ float g_w[NN * KNB];
__device__ int   g_idx[NN * KNB];

// Device-side buffer resolution: keeps kernel_launch free of any host API
// besides kernel launches. ids: 0=g_x, 1=g_y, 2=g_agg, 3=g_h, 4=g_s, -1=arg.
__device__ __forceinline__ const float* resolve_c(const float* p, int id) {
    switch (id) {
        case 0: return g_x;
        case 1: return g_y;
        case 2: return g_agg;
        case 3: return g_h;
        case 4: return g_s;
        default: return p;
    }
}
__device__ __forceinline__ float* resolve_w(float* p, int id) {
    switch (id) {
        case 0: return g_x;
        case 1: return g_y;
        case 2: return g_agg;
        case 3: return g_h;
        case 4: return g_s;
        default: return p;
    }
}

// Monotone float <-> uint key maps (for redux.max over distances).
__device__ __forceinline__ unsigned fkey(float f) {
    unsigned u = __float_as_uint(f);
    return u ^ ((unsigned)((int)u >> 31) | 0x80000000u);
}
__device__ __forceinline__ float unfkey(unsigned k) {
    unsigned m = (k & 0x80000000u) ? 0x80000000u : 0xFFFFFFFFu;
    return __uint_as_float(k ^ m);
}

// ---------------------------------------------------------------------------
// Tiled SGEMM: C[N x MD] = act(A[N x KD] @ W[KD x MD] + b)
// 256 threads: thread (c = t%MD, h = t/MD) owns column c for RPT=MD/8 rows.
// A tile in shared (warp-broadcast LDS.128); W coalesced LDG, depth-2 prefetch.
// ---------------------------------------------------------------------------
template <int KD, int MD, bool RELU>
__global__ void __launch_bounds__(256) gemm_k(const float* __restrict__ Ap, int aid,
                                              const float* __restrict__ W,
                                              const float* __restrict__ B,
                                              float* __restrict__ Cp, int cid) {
    constexpr int RPT = MD / 8;  // rows per thread (MD=128 -> 16, MD=64 -> 8)
    const float* __restrict__ A = resolve_c(Ap, aid);
    float* __restrict__ C = resolve_w(Cp, cid);

    __shared__ float As[32 * KD];
    const int t = threadIdx.x;
    const int c = t % MD;
    const int h = t / MD;
    const int row0 = blockIdx.x * 32;

    {
        const float4* src = reinterpret_cast<const float4*>(A + row0 * KD);
        float4* dst = reinterpret_cast<float4*>(As);
        for (int i = t; i < 8 * KD; i += 256) dst[i] = src[i];
    }
    __syncthreads();

    float acc[RPT];
#pragma unroll
    for (int r = 0; r < RPT; ++r) acc[r] = 0.f;

    const float* Asb = As + (h * RPT) * KD;

    if constexpr (KD % 8 == 0) {
        float w0 = W[0 * MD + c], w1 = W[1 * MD + c];
        float w2 = W[2 * MD + c], w3 = W[3 * MD + c];
        float p0 = W[4 * MD + c], p1 = W[5 * MD + c];
        float p2 = W[6 * MD + c], p3 = W[7 * MD + c];
        for (int k = 0; k < KD; k += 4) {
            float n0 = 0.f, n1 = 0.f, n2 = 0.f, n3 = 0.f;
            if (k + 8 < KD) {
                n0 = W[(k + 8) * MD + c];
                n1 = W[(k + 9) * MD + c];
                n2 = W[(k + 10) * MD + c];
                n3 = W[(k + 11) * MD + c];
            }
#pragma unroll
            for (int r = 0; r < RPT; ++r) {
                float4 a = *reinterpret_cast<const float4*>(&Asb[r * KD + k]);
                float v = acc[r];
                v = fmaf(a.x, w0, v);
                v = fmaf(a.y, w1, v);
                v = fmaf(a.z, w2, v);
                v = fmaf(a.w, w3, v);
                acc[r] = v;
            }
            w0 = p0; w1 = p1; w2 = p2; w3 = p3;
            p0 = n0; p1 = n1; p2 = n2; p3 = n3;
        }
    } else {
        for (int k = 0; k < KD; ++k) {
            float wv = W[k * MD + c];
#pragma unroll
            for (int r = 0; r < RPT; ++r) acc[r] = fmaf(Asb[r * KD + k], wv, acc[r]);
        }
    }

    float bb = B[c];
#pragma unroll
    for (int r = 0; r < RPT; ++r) {
        float v = acc[r] + bb;
        if (RELU) v = fmaxf(v, 0.f);
        C[(row0 + h * RPT + r) * MD + c] = v;
    }
}

// ---------------------------------------------------------------------------
// Two-source SGEMM for lin_out: g_x = [g_y | g_agg] @ W + b, KD=256, MD=128.
// ---------------------------------------------------------------------------
__global__ void __launch_bounds__(256) gemm2_k(const float* __restrict__ W,
                                               const float* __restrict__ B) {
    const float* __restrict__ A1 = g_y;
    const float* __restrict__ A2 = g_agg;
    float* __restrict__ C = g_x;

    __shared__ float As[32 * 256];
    const int t = threadIdx.x;
    const int c = t % 128;
    const int h = t / 128;
    const int row0 = blockIdx.x * 32;

    {
        const float4* s1 = reinterpret_cast<const float4*>(A1 + row0 * 128);
        const float4* s2 = reinterpret_cast<const float4*>(A2 + row0 * 128);
        float4* dst = reinterpret_cast<float4*>(As);
        for (int i = t; i < 32 * 32; i += 256) {
            int r = i >> 5, kq = i & 31;
            dst[r * 64 + kq]      = s1[r * 32 + kq];
            dst[r * 64 + 32 + kq] = s2[r * 32 + kq];
        }
    }
    __syncthreads();

    float acc[16];
#pragma unroll
    for (int r = 0; r < 16; ++r) acc[r] = 0.f;

    const float* Asb = As + (h * 16) * 256;

    float w0 = W[0 * 128 + c], w1 = W[1 * 128 + c];
    float w2 = W[2 * 128 + c], w3 = W[3 * 128 + c];
    float p0 = W[4 * 128 + c], p1 = W[5 * 128 + c];
    float p2 = W[6 * 128 + c], p3 = W[7 * 128 + c];
    for (int k = 0; k < 256; k += 4) {
        float n0 = 0.f, n1 = 0.f, n2 = 0.f, n3 = 0.f;
        if (k + 8 < 256) {
            n0 = W[(k + 8) * 128 + c];
            n1 = W[(k + 9) * 128 + c];
            n2 = W[(k + 10) * 128 + c];
            n3 = W[(k + 11) * 128 + c];
        }
#pragma unroll
        for (int r = 0; r < 16; ++r) {
            float4 a = *reinterpret_cast<const float4*>(&Asb[r * 256 + k]);
            float v = acc[r];
            v = fmaf(a.x, w0, v);
            v = fmaf(a.y, w1, v);
            v = fmaf(a.z, w2, v);
            v = fmaf(a.w, w3, v);
            acc[r] = v;
        }
        w0 = p0; w1 = p1; w2 = p2; w3 = p3;
        p0 = n0; p1 = n1; p2 = n2; p3 = n3;
    }

    float bb = B[c];
#pragma unroll
    for (int r = 0; r < 16; ++r) {
        C[(row0 + h * 16 + r) * 128 + c] = acc[r] + bb;
    }
}

// ---------------------------------------------------------------------------
// Small GEMM: C[N x 4] = act(A[N x 128] @ W[128 x 4] + b).
// ---------------------------------------------------------------------------
template <bool RELU>
__global__ void __launch_bounds__(128) gemm4_k(const float* __restrict__ Ap, int aid,
                                               const float* __restrict__ W,
                                               const float* __restrict__ B,
                                               float* __restrict__ Cp, int cid) {
    const float* __restrict__ A = resolve_c(Ap, aid);
    float* __restrict__ C = resolve_w(Cp, cid);

    __shared__ float As[32][132];
    const int t = threadIdx.x;
    const int row0 = blockIdx.x * 32;

    for (int i = t; i < 32 * 128; i += 128) As[i >> 7][i & 127] = A[row0 * 128 + i];
    __syncthreads();

    const int r = t >> 2, c = t & 3;
    float acc = 0.f;
#pragma unroll 8
    for (int k = 0; k < 128; ++k) acc = fmaf(As[r][k], W[k * 4 + c], acc);

    float v = acc + B[c];
    if (RELU) v = fmaxf(v, 0.f);
    C[(row0 + r) * 4 + c] = v;
}

// ---------------------------------------------------------------------------
// kNN v3: warp-per-row, register-distributed top-40 (lane l: slot0 all lanes,
// slot1 lanes 0..7). Hot loop filters in t-space (t = s2j - 2*dot < worstAdj).
// Rare inserts use redux.sync.max.u32 on flipped-float keys: ~2 REDUX + 1
// ballot per insert instead of two 5-step shfl chains.
// ---------------------------------------------------------------------------
__global__ void __launch_bounds__(256) knn_k() {
    const float* __restrict__ S = g_s;
    int* __restrict__ IDX = g_idx;
    float* __restrict__ WW = g_w;

    constexpr int TJ = 512;
    __shared__ float4 sj[TJ];
    __shared__ float  s2j[TJ];

    const int t = threadIdx.x;
    const int lane = t & 31;
    const int wrp = t >> 5;                 // 8 warps = 8 rows per block
    const int row = blockIdx.x * 8 + wrp;

    const float4 si = reinterpret_cast<const float4*>(S)[row];
    float s2i = si.x * si.x;
    s2i = fmaf(si.y, si.y, s2i);
    s2i = fmaf(si.z, si.z, s2i);
    s2i = fmaf(si.w, si.w, s2i);

    const float INFP = __int_as_float(0x7f800000);
    const float INFN = __int_as_float(0xff800000);

    float bd0 = INFP;
    float bd1 = (lane < 8) ? INFP : INFN;   // -inf sentinel: never argmax
    int bi0 = 0, bi1 = 0;
    float worstAdj = INFP;                  // worst - s2i (warp-uniform)

    for (int base = 0; base < NN; base += TJ) {
        __syncthreads();
        for (int i = t; i < TJ; i += 256) {
            float4 v = reinterpret_cast<const float4*>(S)[base + i];
            float s2 = v.x * v.x;
            s2 = fmaf(v.y, v.y, s2);
            s2 = fmaf(v.z, v.z, s2);
            s2 = fmaf(v.w, v.w, s2);
            sj[i] = v;
            s2j[i] = s2;
        }
        __syncthreads();

#pragma unroll 2
        for (int stp = 0; stp < TJ; stp += 32) {
            float4 vj = sj[stp + lane];
            float dot = si.x * vj.x;
            dot = fmaf(si.y, vj.y, dot);
            dot = fmaf(si.z, vj.z, dot);
            dot = fmaf(si.w, vj.w, dot);
            float tval = fmaf(-2.f, dot, s2j[stp + lane]);  // d - s2i

            unsigned mask = __ballot_sync(FULLMASK, tval < worstAdj);
            while (mask) {
                int src = __ffs(mask) - 1;
                mask &= mask - 1;
                float tc = __shfl_sync(FULLMASK, tval, src);
                if (tc < worstAdj) {
                    float dc = tc + s2i;
                    int jc = base + stp + src;
                    // replace current warp-max slot (redux argmax on keys)
                    unsigned mk = fkey(fmaxf(bd0, bd1));
                    unsigned bmax = __reduce_max_sync(FULLMASK, mk);
                    unsigned sel = __ballot_sync(FULLMASK, mk == bmax);
                    if (lane == __ffs(sel) - 1) {
                        if (bd0 >= bd1) { bd0 = dc; bi0 = jc; }
                        else            { bd1 = dc; bi1 = jc; }
                    }
                    // new threshold
                    mk = fkey(fmaxf(bd0, bd1));
                    bmax = __reduce_max_sync(FULLMASK, mk);
                    worstAdj = unfkey(bmax) - s2i;
                }
            }
        }
    }

    // write out the 40 slots (aggregation is order-invariant)
    IDX[row * KNB + lane] = bi0;
    WW[row * KNB + lane] = expf(-10.f * fmaxf(bd0, 0.f));
    if (lane < 8) {
        IDX[row * KNB + 32 + lane] = bi1;
        WW[row * KNB + 32 + lane] = expf(-10.f * fmaxf(bd1, 0.f));
    }
}

// ---------------------------------------------------------------------------
// Aggregation: g_agg[i] = [mean_k(g_h[idx_k] * w_k), max_k(g_h[idx_k] * w_k)]
// ---------------------------------------------------------------------------
__global__ void __launch_bounds__(256) agg_k() {
    const float* __restrict__ H = g_h;
    const int* __restrict__ IDX = g_idx;
    const float* __restrict__ WW = g_w;
    float* __restrict__ AGG = g_agg;

    __shared__ int   sidx[4][KNB];
    __shared__ float sw[4][KNB];
    const int t = threadIdx.x;
    const int r = t >> 6;
    const int d = t & 63;
    const int row = blockIdx.x * 4 + r;

    if (d < KNB) {
        sidx[r][d] = IDX[row * KNB + d];
        sw[r][d] = WW[row * KNB + d];
    }
    __syncthreads();

    float sum = 0.f, mx = -3.4e38f;
#pragma unroll 4
    for (int k = 0; k < KNB; ++k) {
        int j = sidx[r][k];
        float v = H[j * PROP + d] * sw[r][k];
        sum += v;
        mx = fmaxf(mx, v);
    }
    AGG[row * HID + d]      = sum * (1.f / 40.f);
    AGG[row * HID + 64 + d] = mx;
}

// ---------------------------------------------------------------------------
// Host: full pipeline as a chain of kernel launches (graph-capturable).
// ---------------------------------------------------------------------------
extern "C" void kernel_launch(void* const* d_in, const int* in_sizes, int n_in,
                              void* d_out, int out_size) {
    const float* x_in  = (const float*)d_in[0];
    const float* fc1_W = (const float*)d_in[1];
    const float* fc1_b = (const float*)d_in[2];
    const float* fc2_W = (const float*)d_in[3];
    const float* fc2_b = (const float*)d_in[4];
    const float* gs_W  = (const float*)d_in[5];
    const float* gs_b  = (const float*)d_in[6];
    const float* gh_W  = (const float*)d_in[7];
    const float* gh_b  = (const float*)d_in[8];
    const float* go_W  = (const float*)d_in[9];
    const float* go_b  = (const float*)d_in[10];
    const float* d1_W  = (const float*)d_in[11];
    const float* d1_b  = (const float*)d_in[12];
    const float* d2_W  = (const float*)d_in[13];
    const float* d2_b  = (const float*)d_in[14];
    const float* d3_W  = (const float*)d_in[15];
    const float* d3_b  = (const float*)d_in[16];
    const float* fc3_W = (const float*)d_in[17];
    const float* fc3_b = (const float*)d_in[18];
    const float* fc4_W = (const float*)d_in[19];
    const float* fc4_b = (const float*)d_in[20];
    float* out = (float*)d_out;

    const int GB = NN / 32;  // 512 blocks

    // fc1: x_in -> g_x(relu), fc2: g_x -> g_y(relu)
    gemm_k<9, 128, true><<<GB, 256>>>(x_in, -1, fc1_W, fc1_b, nullptr, 0);
    gemm_k<128, 128, true><<<GB, 256>>>(nullptr, 0, fc2_W, fc2_b, nullptr, 1);

    // x lives in g_y across layers; g_x is the ping-pong scratch.
    for (int i = 0; i < NLAYERS; ++i) {
        gemm4_k<false><<<GB, 128>>>(nullptr, 1, gs_W + i * HID * SPACE, gs_b + i * SPACE, nullptr, 4);
        gemm_k<128, 64, false><<<GB, 256>>>(nullptr, 1, gh_W + i * HID * PROP, gh_b + i * PROP, nullptr, 3);
        knn_k<<<NN / 8, 256>>>();
        agg_k<<<NN / 4, 256>>>();
        gemm2_k<<<GB, 256>>>(go_W + i * 2 * HID * HID, go_b + i * HID);  // [g_y|g_agg] -> g_x
        gemm_k<128, 128, true><<<GB, 256>>>(nullptr, 0, d1_W + i * HID * HID, d1_b + i * HID, nullptr, 1);
        gemm_k<128, 128, true><<<GB, 256>>>(nullptr, 1, d2_W + i * HID * HID, d2_b + i * HID, nullptr, 0);
        gemm_k<128, 128, true><<<GB, 256>>>(nullptr, 0, d3_W + i * HID * HID, d3_b + i * HID, nullptr, 1);
    }

    // fc3: g_y -> g_x(relu), fc4: g_x -> out
    gemm_k<128, 128, true><<<GB, 256>>>(nullptr, 1, fc3_W, fc3_b, nullptr, 0);
    gemm4_k<false><<<GB, 128>>>(nullptr, 0, fc4_W, fc4_b, out, -1);
}